// round 14
// baseline (speedup 1.0000x reference)
#include <cuda_runtime.h>
#include <cuda_bf16.h>
#include <cstdint>
#include <cstddef>

#define TGT 256
#define BSZ 8
#define EDIM 256
#define SRCL 4096
#define PARTSZ (BSZ * TGT * EDIM)
#define SPLITK 4

// Split-K partials for GEMM1 (4 x 2MB)
__device__ float g_O[SPLITK * PARTSZ];

#define SWZ(o) ((o) ^ (((o) >> 3) & 0x70u))

static __device__ __forceinline__ uint32_t smem_u32(const void* p) {
    uint32_t a;
    asm("{ .reg .u64 t; cvta.to.shared.u64 t, %1; cvt.u32.u64 %0, t; }" : "=r"(a) : "l"(p));
    return a;
}
// fp32 pair -> bf16x2 hi + bf16x2 lo (x0 in low half)
static __device__ __forceinline__ void cvt2(float x0, float x1, uint32_t& h, uint32_t& l) {
    asm("cvt.rn.bf16x2.f32 %0, %1, %2;" : "=r"(h) : "f"(x1), "f"(x0));
    float h0 = __uint_as_float(h << 16);
    float h1 = __uint_as_float(h & 0xffff0000u);
    float r0 = x0 - h0;
    float r1 = x1 - h1;
    asm("cvt.rn.bf16x2.f32 %0, %1, %2;" : "=r"(l) : "f"(r1), "f"(r0));
}
static __device__ __forceinline__ void sts64(uint32_t addr, uint32_t a, uint32_t b) {
    asm volatile("st.shared.v2.b32 [%0], {%1, %2};" :: "r"(addr), "r"(a), "r"(b) : "memory");
}
static __device__ __forceinline__ void ldsm_x4(uint32_t& r0, uint32_t& r1, uint32_t& r2,
                                               uint32_t& r3, uint32_t addr) {
    asm volatile("ldmatrix.sync.aligned.m8n8.x4.shared.b16 {%0,%1,%2,%3}, [%4];"
                 : "=r"(r0), "=r"(r1), "=r"(r2), "=r"(r3) : "r"(addr));
}
static __device__ __forceinline__ void ldsm_x2(uint32_t& r0, uint32_t& r1, uint32_t addr) {
    asm volatile("ldmatrix.sync.aligned.m8n8.x2.shared.b16 {%0,%1}, [%2];"
                 : "=r"(r0), "=r"(r1) : "r"(addr));
}
static __device__ __forceinline__ void ldsm_x2t(uint32_t& r0, uint32_t& r1, uint32_t addr) {
    asm volatile("ldmatrix.sync.aligned.m8n8.x2.trans.shared.b16 {%0,%1}, [%2];"
                 : "=r"(r0), "=r"(r1) : "r"(addr));
}
static __device__ __forceinline__ void mma_bf16(float& c0, float& c1, float& c2, float& c3,
                                                uint32_t a0, uint32_t a1, uint32_t a2,
                                                uint32_t a3, uint32_t b0, uint32_t b1) {
    asm volatile(
        "mma.sync.aligned.m16n8k16.row.col.f32.bf16.bf16.f32 "
        "{%0,%1,%2,%3}, {%4,%5,%6,%7}, {%8,%9}, {%0,%1,%2,%3};"
        : "+f"(c0), "+f"(c1), "+f"(c2), "+f"(c3)
        : "r"(a0), "r"(a1), "r"(a2), "r"(a3), "r"(b0), "r"(b1));
}

// ---------------------------------------------------------------------------
// GEMM1: partial X_b[64x128 tile] over K/4 = mask_b @ value_b (+ fused weights copy)
// 256 thr, 8 warps as 2M x 4N (warp 32x32), BK=32, double buffered, 1 sync/chunk,
// 2 CTAs/SM.  A: [m][k] 128B-pad rows SW128 (non-trans ldsm).
//             B: [k][n] bf16, two 4K halves (trans ldsm).
// grid (2 n, 4 m, 8b * 4ks)
// ---------------------------------------------------------------------------
// per-stage: AH 8K | AL 8K | BH 8K | BL 8K = 32K
#define G1_STAGE 32768
#define G1_SMEM  (2 * G1_STAGE)

__global__ void __launch_bounds__(256, 2) gemm1_kernel(
    const float* __restrict__ mask, const float* __restrict__ value,
    float* __restrict__ weights)
{
    extern __shared__ char smem[];
    const uint32_t sb = smem_u32(smem);
    const int tid  = threadIdx.x;
    const int wid  = tid >> 5;
    const int lane = tid & 31;
    const int bx   = blockIdx.x;            // n-tile (0..1)
    const int m0   = blockIdx.y * 64;
    const int n0   = bx * 128;
    const int b    = blockIdx.z >> 2;
    const int ks   = blockIdx.z & 3;
    const int wm   = wid & 1;               // 2 M warps (32 rows)
    const int wn   = wid >> 1;              // 4 N warps (32 cols)
    const int kbase = ks * (SRCL / SPLITK); // KC = 1024
    constexpr int NC = (SRCL / SPLITK) / 32;  // 32 chunks

    const float* Ab = mask + ((size_t)b * TGT + m0) * SRCL;

    const int ar  = tid >> 3;    // 0..31 (A row, +p*32)
    const int ac  = tid & 7;     // A float4 col (k)
    const int br  = tid >> 5;    // 0..7  (B k-row, +q*8)
    const int bc  = tid & 31;    // B float4 col (n)

    float acc[2][4][4];
#pragma unroll
    for (int i = 0; i < 2; i++)
#pragma unroll
        for (int j = 0; j < 4; j++)
#pragma unroll
            for (int q = 0; q < 4; q++) acc[i][j][q] = 0.f;

    float4 aR[2], bR[4];

    auto ldg_chunk = [&](int c) {
        const int k0 = kbase + c * 32;
        const bool docopy = ((c & 1) == bx);
#pragma unroll
        for (int p = 0; p < 2; ++p) {
            int row = p * 32 + ar;
            aR[p] = *(const float4*)(Ab + (size_t)row * SRCL + k0 + ac * 4);
            if (docopy)
                *(float4*)(weights + ((size_t)b * TGT + m0 + row) * SRCL + k0 + ac * 4) = aR[p];
        }
        const float* Bb = value + (size_t)k0 * (BSZ * EDIM) + b * EDIM + n0;
#pragma unroll
        for (int q = 0; q < 4; ++q) {
            int row = q * 8 + br;            // k 0..31
            bR[q] = *(const float4*)(Bb + (size_t)row * (BSZ * EDIM) + bc * 4);
        }
    };

    ldg_chunk(0);

#pragma unroll 1
    for (int c = 0; c < NC; ++c) {
        const uint32_t bufb = sb + (uint32_t)(c & 1) * G1_STAGE;
        // STS A(c): [m][k] rows padded to 128B, SW128 (only first 64B used)
#pragma unroll
        for (int p = 0; p < 2; ++p) {
            int row = p * 32 + ar;
            uint32_t off = SWZ((uint32_t)(row * 128 + ac * 8));
            uint32_t h0, l0, h1, l1;
            cvt2(aR[p].x, aR[p].y, h0, l0);
            cvt2(aR[p].z, aR[p].w, h1, l1);
            sts64(bufb + off, h0, h1);           // A_hi
            sts64(bufb + 8192 + off, l0, l1);    // A_lo
        }
        // STS B(c): [k][n], two 4K halves (n<64 / n>=64)
#pragma unroll
        for (int q = 0; q < 4; ++q) {
            int row = q * 8 + br;
            int n   = bc * 4;
            uint32_t h0, l0, h1, l1;
            cvt2(bR[q].x, bR[q].y, h0, l0);
            cvt2(bR[q].z, bR[q].w, h1, l1);
            uint32_t half = (n >= 64) ? 4096u : 0u;
            uint32_t off  = half + SWZ((uint32_t)(row * 128 + (n & 63) * 2));
            sts64(bufb + 16384 + off, h0, h1);   // B_hi
            sts64(bufb + 24576 + off, l0, l1);   // B_lo
        }
        __syncthreads();

        if (c + 1 < NC) ldg_chunk(c + 1);   // overlaps MMA below

        // MMA over staged chunk: 2 k16 steps
        const int r16 = lane & 15;
        const int hA  = lane >> 4;
#pragma unroll
        for (int kk = 0; kk < 2; ++kk) {
            uint32_t ah[2][4], al[2][4];
#pragma unroll
            for (int mi = 0; mi < 2; ++mi) {
                uint32_t off = SWZ((uint32_t)((wm * 32 + mi * 16 + r16) * 128 + kk * 32 + hA * 16));
                ldsm_x4(ah[mi][0], ah[mi][1], ah[mi][2], ah[mi][3], bufb + off);
                ldsm_x4(al[mi][0], al[mi][1], al[mi][2], al[mi][3], bufb + 8192 + off);
            }
            uint32_t bh[4][2], bl[4][2];
#pragma unroll
            for (int nj = 0; nj < 4; ++nj) {
                int nn = wn * 32 + nj * 8;
                uint32_t half = (nn >= 64) ? 4096u : 0u;
                uint32_t off = half + SWZ((uint32_t)((kk * 16 + r16) * 128 + (nn & 63) * 2));
                ldsm_x2t(bh[nj][0], bh[nj][1], bufb + 16384 + off);
                ldsm_x2t(bl[nj][0], bl[nj][1], bufb + 24576 + off);
            }
#pragma unroll
            for (int mi = 0; mi < 2; ++mi)
#pragma unroll
                for (int nj = 0; nj < 4; ++nj) {
                    mma_bf16(acc[mi][nj][0], acc[mi][nj][1], acc[mi][nj][2], acc[mi][nj][3],
                             ah[mi][0], ah[mi][1], ah[mi][2], ah[mi][3], bh[nj][0], bh[nj][1]);
                    mma_bf16(acc[mi][nj][0], acc[mi][nj][1], acc[mi][nj][2], acc[mi][nj][3],
                             ah[mi][0], ah[mi][1], ah[mi][2], ah[mi][3], bl[nj][0], bl[nj][1]);
                    mma_bf16(acc[mi][nj][0], acc[mi][nj][1], acc[mi][nj][2], acc[mi][nj][3],
                             al[mi][0], al[mi][1], al[mi][2], al[mi][3], bh[nj][0], bh[nj][1]);
                }
        }
    }

    // epilogue: write partial into g_O[ks]
    const int quad = lane >> 2;
    const int qt   = lane & 3;
#pragma unroll
    for (int mi = 0; mi < 2; ++mi)
#pragma unroll
        for (int nj = 0; nj < 4; ++nj) {
            int row = m0 + wm * 32 + mi * 16 + quad;
            int col = n0 + wn * 32 + nj * 8 + qt * 2;
            float* o0 = g_O + (size_t)ks * PARTSZ + ((size_t)b * TGT + row) * EDIM + col;
            *(float2*)o0 = make_float2(acc[mi][nj][0], acc[mi][nj][1]);
            *(float2*)(o0 + 8 * EDIM) = make_float2(acc[mi][nj][2], acc[mi][nj][3]);
        }
}

// ---------------------------------------------------------------------------
// GEMM2: out[32x64] = (sum of 4 partials)[32x256] @ W^T + bias
// 256 thr, 8 warps as 2M x 4N (warp 16x16), BK=64, NC=4, 2-deep LDG prefetch.
// grid (4 n, 8 m, 8 b) = 256 CTAs -> 2 CTAs/SM.
// ---------------------------------------------------------------------------
// per-stage: AH 4K | AL 4K | BH 8K | BL 8K = 24K
#define G2_STAGE 24576
#define G2_SMEM (2 * G2_STAGE)

__global__ void __launch_bounds__(256, 2) gemm2_kernel(
    const float* __restrict__ W, const float* __restrict__ bias,
    float* __restrict__ outp)
{
    extern __shared__ char smem[];
    const uint32_t sb = smem_u32(smem);
    const int tid  = threadIdx.x;
    const int wid  = tid >> 5;
    const int lane = tid & 31;
    const int b    = blockIdx.z;
    const int m0   = blockIdx.y * 32;
    const int n0   = blockIdx.x * 64;
    const int wm   = wid & 1;       // 2 warps in M (16 rows)
    const int wn   = wid >> 1;      // 4 warps in N (16 cols)
    constexpr int NC = EDIM / 64;

    const float* Ag = (const float*)g_O + ((size_t)b * TGT + m0) * EDIM;

    float acc[2][4];
#pragma unroll
    for (int j = 0; j < 2; j++)
#pragma unroll
        for (int q = 0; q < 4; q++) acc[j][q] = 0.f;

    float4 aR[2][2], bR[2][4];
    const int rA = tid >> 4;   // 0..15
    const int c4 = tid & 15;

    auto load_chunk = [&](int c, int s) {
        const int k0 = c * 64;
#pragma unroll
        for (int p = 0; p < 2; ++p) {
            int row = p * 16 + rA;
            const float* a0 = Ag + (size_t)row * EDIM + k0 + c4 * 4;
            float4 v  = *(const float4*)a0;
            float4 v1 = *(const float4*)(a0 + PARTSZ);
            float4 v2 = *(const float4*)(a0 + 2 * PARTSZ);
            float4 v3 = *(const float4*)(a0 + 3 * PARTSZ);
            v.x += v1.x + v2.x + v3.x;
            v.y += v1.y + v2.y + v3.y;
            v.z += v1.z + v2.z + v3.z;
            v.w += v1.w + v2.w + v3.w;
            aR[s][p] = v;
        }
#pragma unroll
        for (int p = 0; p < 4; ++p) {
            int row = p * 16 + rA;
            bR[s][p] = *(const float4*)(W + (size_t)(n0 + row) * EDIM + k0 + c4 * 4);
        }
    };

    load_chunk(0, 0);
    load_chunk(1, 1);

#pragma unroll 1
    for (int c = 0; c < NC; ++c) {
        const int s = c & 1;
        const uint32_t bufb = sb + (uint32_t)s * G2_STAGE;
#pragma unroll
        for (int p = 0; p < 2; ++p) {
            uint32_t o = SWZ((uint32_t)((p * 16 + rA) * 128 + c4 * 8));
            uint32_t h0, l0, h1, l1;
            cvt2(aR[s][p].x, aR[s][p].y, h0, l0);
            cvt2(aR[s][p].z, aR[s][p].w, h1, l1);
            sts64(bufb + o, h0, h1);            // A_hi (4K)
            sts64(bufb + 4096 + o, l0, l1);     // A_lo
        }
#pragma unroll
        for (int p = 0; p < 4; ++p) {
            uint32_t o = SWZ((uint32_t)((p * 16 + rA) * 128 + c4 * 8));
            uint32_t h0, l0, h1, l1;
            cvt2(bR[s][p].x, bR[s][p].y, h0, l0);
            cvt2(bR[s][p].z, bR[s][p].w, h1, l1);
            sts64(bufb + 8192 + o, h0, h1);     // B_hi (8K)
            sts64(bufb + 16384 + o, l0, l1);    // B_lo
        }
        __syncthreads();

        if (c + 2 < NC) load_chunk(c + 2, s);   // 2-deep prefetch

        const int r16 = lane & 15;
        const int hA  = lane >> 4;
        const int r8  = lane & 7;
        const int hb  = (lane >> 3) & 1;
#pragma unroll
        for (int kk = 0; kk < 4; ++kk) {
            uint32_t ah[4], al[4];
            {
                uint32_t o = SWZ((uint32_t)((wm * 16 + r16) * 128 + kk * 32 + hA * 16));
                ldsm_x4(ah[0], ah[1], ah[2], ah[3], bufb + o);
                ldsm_x4(al[0], al[1], al[2], al[3], bufb + 4096 + o);
            }
            uint32_t bh[2][2], bl[2][2];
#pragma unroll
            for (int j = 0; j < 2; ++j) {
                uint32_t o = SWZ((uint32_t)((wn * 16 + j * 8 + r8) * 128 + kk * 32 + hb * 16));
                ldsm_x2(bh[j][0], bh[j][1], bufb + 8192 + o);
                ldsm_x2(bl[j][0], bl[j][1], bufb + 16384 + o);
            }
#pragma unroll
            for (int j = 0; j < 2; ++j) {
                mma_bf16(acc[j][0], acc[j][1], acc[j][2], acc[j][3],
                         ah[0], ah[1], ah[2], ah[3], bh[j][0], bh[j][1]);
                mma_bf16(acc[j][0], acc[j][1], acc[j][2], acc[j][3],
                         ah[0], ah[1], ah[2], ah[3], bl[j][0], bl[j][1]);
                mma_bf16(acc[j][0], acc[j][1], acc[j][2], acc[j][3],
                         al[0], al[1], al[2], al[3], bh[j][0], bh[j][1]);
            }
        }
    }

    const int quad = lane >> 2;
    const int qt   = lane & 3;
#pragma unroll
    for (int j = 0; j < 2; ++j) {
        int row = m0 + wm * 16 + quad;
        int col = n0 + wn * 16 + j * 8 + qt * 2;
        float2 bb = *(const float2*)(bias + col);
        *(float2*)(outp + ((size_t)row * BSZ + b) * EDIM + col) =
            make_float2(acc[j][0] + bb.x, acc[j][1] + bb.y);
        *(float2*)(outp + ((size_t)(row + 8) * BSZ + b) * EDIM + col) =
            make_float2(acc[j][2] + bb.x, acc[j][3] + bb.y);
    }
}

extern "C" void kernel_launch(void* const* d_in, const int* in_sizes, int n_in,
                              void* d_out, int out_size) {
    const float* value = (const float*)d_in[2];
    const float* mask  = (const float*)d_in[3];
    const float* W     = (const float*)d_in[4];
    const float* bias  = (const float*)d_in[5];
    float* out = (float*)d_out;

    float* attn_out = out;                               // (TGT, BSZ, E)
    float* weights  = out + (size_t)TGT * BSZ * EDIM;    // (BSZ, TGT, SRC)

    cudaFuncSetAttribute(gemm1_kernel, cudaFuncAttributeMaxDynamicSharedMemorySize, G1_SMEM);
    cudaFuncSetAttribute(gemm2_kernel, cudaFuncAttributeMaxDynamicSharedMemorySize, G2_SMEM);

    // GEMM1: split-K=4, CTA 64x128, 2 CTAs/SM; fused weights copy
    {
        dim3 grid(2, 4, BSZ * SPLITK);   // 256 CTAs
        gemm1_kernel<<<grid, 256, G1_SMEM>>>(mask, value, weights);
    }
    // GEMM2: out = (sum partials) @ W^T + bias
    {
        dim3 grid(4, 8, BSZ);            // 256 CTAs, 2/SM
        gemm2_kernel<<<grid, 256, G2_SMEM>>>(W, bias, attn_out);
    }
}

// round 17
// speedup vs baseline: 1.5193x; 1.5193x over previous
#include <cuda_runtime.h>
#include <cuda_bf16.h>
#include <cstdint>
#include <cstddef>

#define TGT 256
#define BSZ 8
#define EDIM 256
#define SRCL 4096
#define PARTSZ (BSZ * TGT * EDIM)
#define SPLITK 4

// Split-K partials for GEMM1 (4 x 2MB)
__device__ float g_O[SPLITK * PARTSZ];

#define SWZ(o) ((o) ^ (((o) >> 3) & 0x70u))

static __device__ __forceinline__ uint32_t smem_u32(const void* p) {
    uint32_t a;
    asm("{ .reg .u64 t; cvta.to.shared.u64 t, %1; cvt.u32.u64 %0, t; }" : "=r"(a) : "l"(p));
    return a;
}
// fp32 pair -> bf16x2 hi + bf16x2 lo (x0 in low half)
static __device__ __forceinline__ void cvt2(float x0, float x1, uint32_t& h, uint32_t& l) {
    asm("cvt.rn.bf16x2.f32 %0, %1, %2;" : "=r"(h) : "f"(x1), "f"(x0));
    float h0 = __uint_as_float(h << 16);
    float h1 = __uint_as_float(h & 0xffff0000u);
    float r0 = x0 - h0;
    float r1 = x1 - h1;
    asm("cvt.rn.bf16x2.f32 %0, %1, %2;" : "=r"(l) : "f"(r1), "f"(r0));
}
static __device__ __forceinline__ void sts64(uint32_t addr, uint32_t a, uint32_t b) {
    asm volatile("st.shared.v2.b32 [%0], {%1, %2};" :: "r"(addr), "r"(a), "r"(b) : "memory");
}
static __device__ __forceinline__ void ldsm_x4(uint32_t& r0, uint32_t& r1, uint32_t& r2,
                                               uint32_t& r3, uint32_t addr) {
    asm volatile("ldmatrix.sync.aligned.m8n8.x4.shared.b16 {%0,%1,%2,%3}, [%4];"
                 : "=r"(r0), "=r"(r1), "=r"(r2), "=r"(r3) : "r"(addr));
}
static __device__ __forceinline__ void ldsm_x2(uint32_t& r0, uint32_t& r1, uint32_t addr) {
    asm volatile("ldmatrix.sync.aligned.m8n8.x2.shared.b16 {%0,%1}, [%2];"
                 : "=r"(r0), "=r"(r1) : "r"(addr));
}
static __device__ __forceinline__ void ldsm_x2t(uint32_t& r0, uint32_t& r1, uint32_t addr) {
    asm volatile("ldmatrix.sync.aligned.m8n8.x2.trans.shared.b16 {%0,%1}, [%2];"
                 : "=r"(r0), "=r"(r1) : "r"(addr));
}
static __device__ __forceinline__ void mma_bf16(float& c0, float& c1, float& c2, float& c3,
                                                uint32_t a0, uint32_t a1, uint32_t a2,
                                                uint32_t a3, uint32_t b0, uint32_t b1) {
    asm volatile(
        "mma.sync.aligned.m16n8k16.row.col.f32.bf16.bf16.f32 "
        "{%0,%1,%2,%3}, {%4,%5,%6,%7}, {%8,%9}, {%0,%1,%2,%3};"
        : "+f"(c0), "+f"(c1), "+f"(c2), "+f"(c3)
        : "r"(a0), "r"(a1), "r"(a2), "r"(a3), "r"(b0), "r"(b1));
}

// ---------------------------------------------------------------------------
// GEMM1: partial X_b[128x64 tile] over K/4 = mask_b @ value_b (+ fused weights copy)
// 256 thr, 8 warps as 4M x 2N (warp 32x32), BK=64, NC=16, double buffered,
// 1 sync/chunk, 2 CTAs/SM.
// A: [m][k] bf16 128B rows SW128 (non-trans ldsm). B: [k][n] bf16 (trans ldsm).
// grid (4 n, 2 m, 8b * 4ks) = 256 CTAs
// ---------------------------------------------------------------------------
// per-stage: AH 16K | AL 16K | BH 8K | BL 8K = 48K
#define G1_STAGE 49152
#define G1_SMEM  (2 * G1_STAGE)

__global__ void __launch_bounds__(256, 2) gemm1_kernel(
    const float* __restrict__ mask, const float* __restrict__ value,
    float* __restrict__ weights)
{
    extern __shared__ char smem[];
    const uint32_t sb = smem_u32(smem);
    const int tid  = threadIdx.x;
    const int wid  = tid >> 5;
    const int lane = tid & 31;
    const int bx   = blockIdx.x;            // n-tile (0..3)
    const int m0   = blockIdx.y * 128;
    const int n0   = bx * 64;
    const int b    = blockIdx.z >> 2;
    const int ks   = blockIdx.z & 3;
    const int wm   = wid & 3;               // 4 M warps (32 rows)
    const int wn   = wid >> 2;              // 2 N warps (32 cols)
    const int kbase = ks * (SRCL / SPLITK); // KC = 1024
    constexpr int NC = (SRCL / SPLITK) / 64;  // 16 chunks

    const float* Ab = mask + ((size_t)b * TGT + m0) * SRCL;

    const int ar  = tid >> 4;    // 0..15 (A row, +p*16)
    const int ac  = tid & 15;    // A float4 col (k)
    const int br  = tid >> 4;    // 0..15 (B k-row, +q*16)
    const int bc  = tid & 15;    // B float4 col (n)

    float acc[2][4][4];
#pragma unroll
    for (int i = 0; i < 2; i++)
#pragma unroll
        for (int j = 0; j < 4; j++)
#pragma unroll
            for (int q = 0; q < 4; q++) acc[i][j][q] = 0.f;

    float4 aR[8], bR[4];

    auto ldg_chunk = [&](int c) {
        const int k0 = kbase + c * 64;
        const bool docopy = ((c & 1) == bx);   // bx 0/1 copy even/odd chunks
#pragma unroll
        for (int p = 0; p < 8; ++p) {
            int row = p * 16 + ar;
            aR[p] = *(const float4*)(Ab + (size_t)row * SRCL + k0 + ac * 4);
            if (docopy)
                *(float4*)(weights + ((size_t)b * TGT + m0 + row) * SRCL + k0 + ac * 4) = aR[p];
        }
        const float* Bb = value + (size_t)k0 * (BSZ * EDIM) + b * EDIM + n0;
#pragma unroll
        for (int q = 0; q < 4; ++q) {
            int row = q * 16 + br;           // k 0..63
            bR[q] = *(const float4*)(Bb + (size_t)row * (BSZ * EDIM) + bc * 4);
        }
    };

    ldg_chunk(0);

#pragma unroll 1
    for (int c = 0; c < NC; ++c) {
        const uint32_t bufb = sb + (uint32_t)(c & 1) * G1_STAGE;
        // STS A(c): [m][k] 128 rows x 64k (128B rows), SW128
#pragma unroll
        for (int p = 0; p < 8; ++p) {
            int row = p * 16 + ar;
            uint32_t off = SWZ((uint32_t)(row * 128 + ac * 8));
            uint32_t h0, l0, h1, l1;
            cvt2(aR[p].x, aR[p].y, h0, l0);
            cvt2(aR[p].z, aR[p].w, h1, l1);
            sts64(bufb + off, h0, h1);           // A_hi
            sts64(bufb + 16384 + off, l0, l1);   // A_lo
        }
        // STS B(c): [k][n] 64 rows x 64n (128B rows), SW128
#pragma unroll
        for (int q = 0; q < 4; ++q) {
            int row = q * 16 + br;
            uint32_t off = SWZ((uint32_t)(row * 128 + bc * 8));
            uint32_t h0, l0, h1, l1;
            cvt2(bR[q].x, bR[q].y, h0, l0);
            cvt2(bR[q].z, bR[q].w, h1, l1);
            sts64(bufb + 32768 + off, h0, h1);   // B_hi
            sts64(bufb + 40960 + off, l0, l1);   // B_lo
        }
        __syncthreads();

        if (c + 1 < NC) ldg_chunk(c + 1);   // overlaps MMA below

        // MMA over staged chunk: 4 k16 steps
        const int r16 = lane & 15;
        const int hA  = lane >> 4;
#pragma unroll
        for (int kk = 0; kk < 4; ++kk) {
            uint32_t ah[2][4], al[2][4];
#pragma unroll
            for (int mi = 0; mi < 2; ++mi) {
                uint32_t off = SWZ((uint32_t)((wm * 32 + mi * 16 + r16) * 128 + kk * 32 + hA * 16));
                ldsm_x4(ah[mi][0], ah[mi][1], ah[mi][2], ah[mi][3], bufb + off);
                ldsm_x4(al[mi][0], al[mi][1], al[mi][2], al[mi][3], bufb + 16384 + off);
            }
            uint32_t bh[4][2], bl[4][2];
#pragma unroll
            for (int nj = 0; nj < 4; ++nj) {
                int nn = wn * 32 + nj * 8;
                uint32_t off = SWZ((uint32_t)((kk * 16 + r16) * 128 + nn * 2));
                ldsm_x2t(bh[nj][0], bh[nj][1], bufb + 32768 + off);
                ldsm_x2t(bl[nj][0], bl[nj][1], bufb + 40960 + off);
            }
#pragma unroll
            for (int mi = 0; mi < 2; ++mi)
#pragma unroll
                for (int nj = 0; nj < 4; ++nj) {
                    mma_bf16(acc[mi][nj][0], acc[mi][nj][1], acc[mi][nj][2], acc[mi][nj][3],
                             ah[mi][0], ah[mi][1], ah[mi][2], ah[mi][3], bh[nj][0], bh[nj][1]);
                    mma_bf16(acc[mi][nj][0], acc[mi][nj][1], acc[mi][nj][2], acc[mi][nj][3],
                             ah[mi][0], ah[mi][1], ah[mi][2], ah[mi][3], bl[nj][0], bl[nj][1]);
                    mma_bf16(acc[mi][nj][0], acc[mi][nj][1], acc[mi][nj][2], acc[mi][nj][3],
                             al[mi][0], al[mi][1], al[mi][2], al[mi][3], bh[nj][0], bh[nj][1]);
                }
        }
    }

    // epilogue: write partial into g_O[ks]
    const int quad = lane >> 2;
    const int qt   = lane & 3;
#pragma unroll
    for (int mi = 0; mi < 2; ++mi)
#pragma unroll
        for (int nj = 0; nj < 4; ++nj) {
            int row = m0 + wm * 32 + mi * 16 + quad;
            int col = n0 + wn * 32 + nj * 8 + qt * 2;
            float* o0 = g_O + (size_t)ks * PARTSZ + ((size_t)b * TGT + row) * EDIM + col;
            *(float2*)o0 = make_float2(acc[mi][nj][0], acc[mi][nj][1]);
            *(float2*)(o0 + 8 * EDIM) = make_float2(acc[mi][nj][2], acc[mi][nj][3]);
        }
}

// ---------------------------------------------------------------------------
// GEMM2: out[32x64] = (sum of 4 partials)[32x256] @ W^T + bias  (R10-proven)
// 256 thr, 8 warps as 2M x 4N (warp 16x16), BK=64, NC=4.
// grid (4 n, 8 m, 8 b) = 256 CTAs -> 2 CTAs/SM.
// ---------------------------------------------------------------------------
// per-stage: AH 4K | AL 4K | BH 8K | BL 8K = 24K
#define G2_STAGE 24576
#define G2_SMEM (2 * G2_STAGE)

__global__ void __launch_bounds__(256, 2) gemm2_kernel(
    const float* __restrict__ W, const float* __restrict__ bias,
    float* __restrict__ outp)
{
    extern __shared__ char smem[];
    const uint32_t sb = smem_u32(smem);
    const int tid  = threadIdx.x;
    const int wid  = tid >> 5;
    const int lane = tid & 31;
    const int b    = blockIdx.z;
    const int m0   = blockIdx.y * 32;
    const int n0   = blockIdx.x * 64;
    const int wm   = wid & 1;       // 2 warps in M (16 rows)
    const int wn   = wid >> 1;      // 4 warps in N (16 cols)
    constexpr int NC = EDIM / 64;

    const float* Ag = (const float*)g_O + ((size_t)b * TGT + m0) * EDIM;

    float acc[2][4];
#pragma unroll
    for (int j = 0; j < 2; j++)
#pragma unroll
        for (int q = 0; q < 4; q++) acc[j][q] = 0.f;

    float4 aR[2], bR[4];
    const int rA = tid >> 4;   // 0..15
    const int c4 = tid & 15;

    auto load_chunk = [&](int k0) {
#pragma unroll
        for (int p = 0; p < 2; ++p) {
            int row = p * 16 + rA;
            const float* a0 = Ag + (size_t)row * EDIM + k0 + c4 * 4;
            float4 v  = *(const float4*)a0;
            float4 v1 = *(const float4*)(a0 + PARTSZ);
            float4 v2 = *(const float4*)(a0 + 2 * PARTSZ);
            float4 v3 = *(const float4*)(a0 + 3 * PARTSZ);
            v.x += v1.x + v2.x + v3.x;
            v.y += v1.y + v2.y + v3.y;
            v.z += v1.z + v2.z + v3.z;
            v.w += v1.w + v2.w + v3.w;
            aR[p] = v;
        }
#pragma unroll
        for (int p = 0; p < 4; ++p) {
            int row = p * 16 + rA;
            bR[p] = *(const float4*)(W + (size_t)(n0 + row) * EDIM + k0 + c4 * 4);
        }
    };

    load_chunk(0);

#pragma unroll 1
    for (int c = 0; c < NC; ++c) {
        const uint32_t bufb = sb + (uint32_t)(c & 1) * G2_STAGE;
#pragma unroll
        for (int p = 0; p < 2; ++p) {
            uint32_t o = SWZ((uint32_t)((p * 16 + rA) * 128 + c4 * 8));
            uint32_t h0, l0, h1, l1;
            cvt2(aR[p].x, aR[p].y, h0, l0);
            cvt2(aR[p].z, aR[p].w, h1, l1);
            sts64(bufb + o, h0, h1);            // A_hi (4K)
            sts64(bufb + 4096 + o, l0, l1);     // A_lo
        }
#pragma unroll
        for (int p = 0; p < 4; ++p) {
            uint32_t o = SWZ((uint32_t)((p * 16 + rA) * 128 + c4 * 8));
            uint32_t h0, l0, h1, l1;
            cvt2(bR[p].x, bR[p].y, h0, l0);
            cvt2(bR[p].z, bR[p].w, h1, l1);
            sts64(bufb + 8192 + o, h0, h1);     // B_hi (8K)
            sts64(bufb + 16384 + o, l0, l1);    // B_lo
        }
        __syncthreads();

        if (c + 1 < NC) load_chunk((c + 1) * 64);

        const int r16 = lane & 15;
        const int hA  = lane >> 4;
        const int r8  = lane & 7;
        const int hb  = (lane >> 3) & 1;
#pragma unroll
        for (int kk = 0; kk < 4; ++kk) {
            uint32_t ah[4], al[4];
            {
                uint32_t o = SWZ((uint32_t)((wm * 16 + r16) * 128 + kk * 32 + hA * 16));
                ldsm_x4(ah[0], ah[1], ah[2], ah[3], bufb + o);
                ldsm_x4(al[0], al[1], al[2], al[3], bufb + 4096 + o);
            }
            uint32_t bh[2][2], bl[2][2];
#pragma unroll
            for (int j = 0; j < 2; ++j) {
                uint32_t o = SWZ((uint32_t)((wn * 16 + j * 8 + r8) * 128 + kk * 32 + hb * 16));
                ldsm_x2(bh[j][0], bh[j][1], bufb + 8192 + o);
                ldsm_x2(bl[j][0], bl[j][1], bufb + 16384 + o);
            }
#pragma unroll
            for (int j = 0; j < 2; ++j) {
                mma_bf16(acc[j][0], acc[j][1], acc[j][2], acc[j][3],
                         ah[0], ah[1], ah[2], ah[3], bh[j][0], bh[j][1]);
                mma_bf16(acc[j][0], acc[j][1], acc[j][2], acc[j][3],
                         ah[0], ah[1], ah[2], ah[3], bl[j][0], bl[j][1]);
                mma_bf16(acc[j][0], acc[j][1], acc[j][2], acc[j][3],
                         al[0], al[1], al[2], al[3], bh[j][0], bh[j][1]);
            }
        }
    }

    const int quad = lane >> 2;
    const int qt   = lane & 3;
#pragma unroll
    for (int j = 0; j < 2; ++j) {
        int row = m0 + wm * 16 + quad;
        int col = n0 + wn * 16 + j * 8 + qt * 2;
        float2 bb = *(const float2*)(bias + col);
        *(float2*)(outp + ((size_t)row * BSZ + b) * EDIM + col) =
            make_float2(acc[j][0] + bb.x, acc[j][1] + bb.y);
        *(float2*)(outp + ((size_t)(row + 8) * BSZ + b) * EDIM + col) =
            make_float2(acc[j][2] + bb.x, acc[j][3] + bb.y);
    }
}

extern "C" void kernel_launch(void* const* d_in, const int* in_sizes, int n_in,
                              void* d_out, int out_size) {
    const float* value = (const float*)d_in[2];
    const float* mask  = (const float*)d_in[3];
    const float* W     = (const float*)d_in[4];
    const float* bias  = (const float*)d_in[5];
    float* out = (float*)d_out;

    float* attn_out = out;                               // (TGT, BSZ, E)
    float* weights  = out + (size_t)TGT * BSZ * EDIM;    // (BSZ, TGT, SRC)

    cudaFuncSetAttribute(gemm1_kernel, cudaFuncAttributeMaxDynamicSharedMemorySize, G1_SMEM);
    cudaFuncSetAttribute(gemm2_kernel, cudaFuncAttributeMaxDynamicSharedMemorySize, G2_SMEM);

    // GEMM1: split-K=4, CTA 128m x 64n, BK=64, 2 CTAs/SM; fused weights copy
    {
        dim3 grid(4, 2, BSZ * SPLITK);   // 256 CTAs
        gemm1_kernel<<<grid, 256, G1_SMEM>>>(mask, value, weights);
    }
    // GEMM2: out = (sum of 4 partials) @ W^T + bias
    {
        dim3 grid(4, 8, BSZ);            // 256 CTAs, 2/SM
        gemm2_kernel<<<grid, 256, G2_SMEM>>>(W, bias, attn_out);
    }
}